// round 7
// baseline (speedup 1.0000x reference)
#include <cuda_runtime.h>
#include <cuda_bf16.h>
#include <math.h>

#define NB    256      // batch
#define NM    6        // goals
#define INC   448
#define EMB   32
#define NHEAD 8
#define DFF   2048
#define OBS   20
#define HOR   30
#define DD    512      // model dim
#define LBUF  50
#define HD    64
#define BMT   1536     // NB*NM

// ------------------------- scratch (static device globals) -------------------------
__device__ __align__(256) float g_cfeat[NB*1536];      // feat @ W_qkv[64:512] + b_qkv
__device__ __align__(256) float g_cffus[NB*448];       // feat @ W_fus[519:967] + b_fus
__device__ __align__(256) float g_Wcat[64*2560];       // tf32; cols 1536:2560 = emb->eKV map
__device__ __align__(256) float g_Wor[512*512];        // tf32-rounded W_o
__device__ __align__(256) float g_Wff1r[512*2048];     // tf32-rounded W_ff1
__device__ __align__(256) float g_Wff2r[2048*512];     // tf32-rounded W_ff2
__device__ __align__(256) float g_Wfusr[512*448];      // tf32-rounded W_fus[0:512]
__device__ __align__(256) float g_eobs[OBS*NB*32];     // relu(obs @ W_emb + b) per (l,b)
__device__ __align__(256) __nv_bfloat16 g_eKVo[(size_t)OBS*NB*1024];   // obs eKV, per-b
__device__ __align__(256) __nv_bfloat16 g_eKV[(size_t)HOR*BMT*1024];   // rollout eKV, per-bm
__device__ __align__(256) float g_E[BMT*64];           // [extras(32) | embPrev(32)] tf32
__device__ __align__(256) float g_xlast[BMT*DD];
__device__ __align__(256) float g_rowfus[BMT*448];
__device__ __align__(256) float g_QKVC[BMT*1536];      // q | ck | cv
__device__ __align__(256) float g_ctx[BMT*DD];         // tf32-rounded
__device__ __align__(256) float g_wo[BMT*DD];
__device__ __align__(256) float g_wob[BMT*DD];         // split-K half; also eKV dummy @f=OBS
__device__ __align__(256) float g_h1[BMT*DD];          // tf32-rounded
__device__ __align__(256) float g_ff1[BMT*DFF];        // tf32-rounded
__device__ __align__(256) float g_ff2[BMT*DD];
__device__ __align__(256) float g_ff2b[BMT*DD];
__device__ __align__(256) float g_h2[BMT*DD];          // tf32-rounded
__device__ __align__(256) float g_fus[BMT*448];
__device__ __align__(256) float g_fusb[BMT*448];
__device__ __align__(256) float g_emb[BMT*EMB];        // emb of frame f-1
__device__ __align__(256) float g_last[BMT*2];

// --------------------------- TF32 helpers ----------------------------------------
__device__ __forceinline__ unsigned f2tf(float x) {
    unsigned u;
    asm("cvt.rna.tf32.f32 %0, %1;" : "=r"(u) : "f"(x));
    return u;
}
__device__ __forceinline__ float tfr(float x) { return __uint_as_float(f2tf(x)); }

__device__ __forceinline__ void mma8(float* d, const unsigned* a, const unsigned* b) {
    asm volatile(
        "mma.sync.aligned.m16n8k8.row.col.f32.tf32.tf32.f32 "
        "{%0,%1,%2,%3}, {%4,%5,%6,%7}, {%8,%9}, {%0,%1,%2,%3};"
        : "+f"(d[0]), "+f"(d[1]), "+f"(d[2]), "+f"(d[3])
        : "r"(a[0]), "r"(a[1]), "r"(a[2]), "r"(a[3]), "r"(b[0]), "r"(b[1]));
}

// =============== pipelined TF32 GEMM (cp.async, 3-stage) ==========================
// Operands MUST be tf32-pre-rounded (MMA consumes raw fp32 bits, lossless).
// Block tile 128 x NT (NT=128 or 64), BK=32, 256 threads, 1 sync per slab.
// gridDim.z==2 -> split-K: z=1 does upper half into C2 (no bias/rowadd).
// EK != null: blocks with col0 >= ekcol write bf16 to EK (ld 1024) instead of C.
template<int NT>
__global__ void k_gemmp(const float* __restrict__ A, int lda,
                        const float* __restrict__ Bm, int ldb,
                        float* __restrict__ C, int ldc, int K,
                        const float* __restrict__ bias,
                        const float* __restrict__ rowadd, int ramod, int ldra,
                        int relu, int otf32, float* __restrict__ C2,
                        __nv_bfloat16* __restrict__ EK, int ekcol)
{
    constexpr int BPAD = NT + 4;
    constexpr int ASZ = 128 * 36;
    constexpr int BSZ = 32 * BPAD;
    extern __shared__ float sm[];
    float* AsB = sm;            // 3 stages
    float* BsB = sm + 3 * ASZ;  // 3 stages

    if (blockIdx.z) { A += K; Bm += (size_t)K * ldb; C = C2; bias = 0; rowadd = 0; }

    const int row0 = blockIdx.y * 128, col0 = blockIdx.x * NT;
    const int tid = threadIdx.x, warp = tid >> 5, lane = tid & 31;
    constexpr int WN = (NT == 128) ? 4 : 2;   // warps along n
    constexpr int MI = (NT == 128) ? 4 : 2;   // 16-row m-frags per warp
    const int wm = warp / WN, wn = warp % WN;
    const int l4 = lane >> 2, lm4 = lane & 3;
    const int ar = tid >> 3, akq = (tid & 7) * 4;
    constexpr int NSEG = NT / 4;              // float4 per B row
    constexpr int BIT = 32 * NSEG / 256;      // B cp.async per thread
    const int brow0 = tid / NSEG, bc4 = (tid % NSEG) * 4;

    float acc[MI][4][4] = {};

    auto load = [&](int k0, int s) {
        float* as = AsB + s * ASZ;
        float* bs = BsB + s * BSZ;
#pragma unroll
        for (int i = 0; i < 4; i++) {
            unsigned d = (unsigned)__cvta_generic_to_shared(as + (ar + i * 32) * 36 + akq);
            const float* g = A + (size_t)(row0 + ar + i * 32) * lda + k0 + akq;
            asm volatile("cp.async.cg.shared.global [%0],[%1],16;\n" :: "r"(d), "l"(g));
        }
#pragma unroll
        for (int i = 0; i < BIT; i++) {
            int row = brow0 + i * (256 / NSEG);
            unsigned d = (unsigned)__cvta_generic_to_shared(bs + row * BPAD + bc4);
            const float* g = Bm + (size_t)(k0 + row) * ldb + col0 + bc4;
            asm volatile("cp.async.cg.shared.global [%0],[%1],16;\n" :: "r"(d), "l"(g));
        }
        asm volatile("cp.async.commit_group;\n");
    };

    const int nslab = K >> 5;
    load(0, 0);
    if (nslab > 1) load(32, 1); else asm volatile("cp.async.commit_group;\n");

    for (int k = 0; k < nslab; k++) {
        asm volatile("cp.async.wait_group 1;\n");
        __syncthreads();
        if (k + 2 < nslab) load((k + 2) * 32, (k + 2) % 3);
        else               asm volatile("cp.async.commit_group;\n");
        const float* as = AsB + (k % 3) * ASZ;
        const float* bs = BsB + (k % 3) * BSZ;
#pragma unroll
        for (int ks = 0; ks < 4; ks++) {
            const int kk = ks * 8;
            unsigned a[MI][4], b[4][2];
#pragma unroll
            for (int mi = 0; mi < MI; mi++) {
                int mb = wm * (MI * 16) + mi * 16 + l4;
                a[mi][0] = __float_as_uint(as[mb * 36 + kk + lm4]);
                a[mi][1] = __float_as_uint(as[(mb + 8) * 36 + kk + lm4]);
                a[mi][2] = __float_as_uint(as[mb * 36 + kk + lm4 + 4]);
                a[mi][3] = __float_as_uint(as[(mb + 8) * 36 + kk + lm4 + 4]);
            }
#pragma unroll
            for (int nj = 0; nj < 4; nj++) {
                int nb = wn * 32 + nj * 8 + l4;
                b[nj][0] = __float_as_uint(bs[(kk + lm4) * BPAD + nb]);
                b[nj][1] = __float_as_uint(bs[(kk + lm4 + 4) * BPAD + nb]);
            }
#pragma unroll
            for (int mi = 0; mi < MI; mi++)
#pragma unroll
                for (int nj = 0; nj < 4; nj++)
                    mma8(acc[mi][nj], a[mi], b[nj]);
        }
    }

    // epilogue
    const bool ekreg = (EK != 0) && (col0 >= ekcol);
#pragma unroll
    for (int mi = 0; mi < MI; mi++) {
        const int rb = row0 + wm * (MI * 16) + mi * 16 + l4;
#pragma unroll
        for (int nj = 0; nj < 4; nj++) {
            const int c = col0 + wn * 32 + nj * 8 + lm4 * 2;
#pragma unroll
            for (int h = 0; h < 2; h++) {
                const int r = rb + h * 8;
                float v0 = acc[mi][nj][h * 2 + 0];
                float v1 = acc[mi][nj][h * 2 + 1];
                if (ekreg) {
                    *(__nv_bfloat162*)(EK + (size_t)r * 1024 + (c - ekcol)) =
                        __floats2bfloat162_rn(v0, v1);
                    continue;
                }
                if (bias) { v0 += bias[c]; v1 += bias[c + 1]; }
                if (rowadd) {
                    const float* ra = rowadd + (size_t)(r % ramod) * ldra + c;
                    v0 += ra[0]; v1 += ra[1];
                }
                if (relu) { v0 = fmaxf(v0, 0.f); v1 = fmaxf(v1, 0.f); }
                if (otf32) { v0 = tfr(v0); v1 = tfr(v1); }
                *(float2*)(C + (size_t)r * ldc + c) = make_float2(v0, v1);
            }
        }
    }
}

// --------------- legacy converting GEMM core (setup paths) ------------------------
__device__ __forceinline__ void gemm0_body(const float* __restrict__ A, int lda,
                                           const float* __restrict__ Bm, int ldb,
                                           void* __restrict__ Cv, int ldc, int K,
                                           const float* __restrict__ bias, int obf16)
{
    __shared__ __align__(16) unsigned As[128 * 36];
    __shared__ __align__(16) unsigned Bs[32 * 68];
    const int row0 = blockIdx.y * 128, col0 = blockIdx.x * 64;
    const int tid = threadIdx.x;
    const int warp = tid >> 5, lane = tid & 31;
    const int wm = warp >> 1, wn = warp & 1;
    const int l4 = lane >> 2, lm4 = lane & 3;
    const int ar = tid >> 3, akq = (tid & 7) * 4;
    const int br = tid >> 4, bcq = (tid & 15) * 4;

    float acc[2][4][4] = {};
    float4 pa[4], pb[2];
#pragma unroll
    for (int it = 0; it < 4; it++)
        pa[it] = *(const float4*)(A + (size_t)(row0 + ar + it * 32) * lda + akq);
#pragma unroll
    for (int it = 0; it < 2; it++)
        pb[it] = *(const float4*)(Bm + (size_t)(br + it * 16) * ldb + col0 + bcq);

    for (int k0 = 0; k0 < K; k0 += 32) {
#pragma unroll
        for (int it = 0; it < 4; it++) {
            unsigned* p = &As[(ar + it * 32) * 36 + akq];
            p[0] = f2tf(pa[it].x); p[1] = f2tf(pa[it].y);
            p[2] = f2tf(pa[it].z); p[3] = f2tf(pa[it].w);
        }
#pragma unroll
        for (int it = 0; it < 2; it++) {
            unsigned* p = &Bs[(br + it * 16) * 68 + bcq];
            p[0] = f2tf(pb[it].x); p[1] = f2tf(pb[it].y);
            p[2] = f2tf(pb[it].z); p[3] = f2tf(pb[it].w);
        }
        __syncthreads();
        if (k0 + 32 < K) {
#pragma unroll
            for (int it = 0; it < 4; it++)
                pa[it] = *(const float4*)(A + (size_t)(row0 + ar + it * 32) * lda + k0 + 32 + akq);
#pragma unroll
            for (int it = 0; it < 2; it++)
                pb[it] = *(const float4*)(Bm + (size_t)(k0 + 32 + br + it * 16) * ldb + col0 + bcq);
        }
#pragma unroll
        for (int ks = 0; ks < 4; ks++) {
            const int kk = ks * 8;
            unsigned a[2][4], b[4][2];
#pragma unroll
            for (int mi = 0; mi < 2; mi++) {
                int mb = wm * 32 + mi * 16 + l4;
                a[mi][0] = As[mb * 36 + kk + lm4];
                a[mi][1] = As[(mb + 8) * 36 + kk + lm4];
                a[mi][2] = As[mb * 36 + kk + lm4 + 4];
                a[mi][3] = As[(mb + 8) * 36 + kk + lm4 + 4];
            }
#pragma unroll
            for (int nj = 0; nj < 4; nj++) {
                int nb = wn * 32 + nj * 8 + l4;
                b[nj][0] = Bs[(kk + lm4) * 68 + nb];
                b[nj][1] = Bs[(kk + lm4 + 4) * 68 + nb];
            }
#pragma unroll
            for (int mi = 0; mi < 2; mi++)
#pragma unroll
                for (int nj = 0; nj < 4; nj++)
                    mma8(acc[mi][nj], a[mi], b[nj]);
        }
        __syncthreads();
    }
#pragma unroll
    for (int mi = 0; mi < 2; mi++) {
        const int rb = row0 + wm * 32 + mi * 16 + l4;
#pragma unroll
        for (int nj = 0; nj < 4; nj++) {
            const int c = col0 + wn * 32 + nj * 8 + lm4 * 2;
#pragma unroll
            for (int h = 0; h < 2; h++) {
                const int r = rb + h * 8;
                float v0 = acc[mi][nj][h * 2 + 0];
                float v1 = acc[mi][nj][h * 2 + 1];
                if (bias) { v0 += bias[c]; v1 += bias[c + 1]; }
                if (obf16) {
                    *(__nv_bfloat162*)((__nv_bfloat16*)Cv + (size_t)r * ldc + c) =
                        __floats2bfloat162_rn(v0, v1);
                } else {
                    *(float2*)((float*)Cv + (size_t)r * ldc + c) = make_float2(v0, v1);
                }
            }
        }
    }
}

__global__ void k_gemm0(const float* __restrict__ A, int lda,
                        const float* __restrict__ Bm, int ldb,
                        void* __restrict__ Cv, int ldc, int K,
                        const float* __restrict__ bias, int obf16)
{
    gemm0_body(A, lda, Bm, ldb, Cv, ldc, K, bias, obf16);
}

// dual-config setup GEMM: z=0 -> cfeat, z=1 -> cffus (both A=feat, K=448)
__global__ void k_gemm0d(const float* __restrict__ A, int lda, int K,
                         const float* __restrict__ B0, int ldb0,
                         float* __restrict__ C0, int ldc0,
                         const float* __restrict__ bias0, int nx0,
                         const float* __restrict__ B1, int ldb1,
                         float* __restrict__ C1, int ldc1,
                         const float* __restrict__ bias1, int nx1)
{
    if (blockIdx.z == 0) {
        if ((int)blockIdx.x >= nx0) return;
        gemm0_body(A, lda, B0, ldb0, C0, ldc0, K, bias0, 0);
    } else {
        if ((int)blockIdx.x >= nx1) return;
        gemm0_body(A, lda, B1, ldb1, C1, ldc1, K, bias1, 0);
    }
}

// ------------------------- one-time: round all weights + build Wcat ---------------
__global__ void k_setup(const float* __restrict__ Wqkv, const float* __restrict__ Wo,
                        const float* __restrict__ Wff1, const float* __restrict__ Wff2,
                        const float* __restrict__ Wfus)
{
    int i = blockIdx.x * 256 + threadIdx.x;
    const int N0 = 64 * 2560, N1 = 512 * 512, N2 = 512 * 2048,
              N3 = 2048 * 512, N4 = 512 * 448;
    if (i < N0) {
        int r = i / 2560, c = i - r * 2560;
        float v;
        if (c < 1536)
            v = (r < 32) ? Wqkv[(32 + r) * 1536 + c]
                         : ((c < 512) ? Wqkv[(r - 32) * 1536 + c] : 0.f);
        else
            v = (r < 32) ? 0.f : Wqkv[(r - 32) * 1536 + 512 + (c - 1536)];
        g_Wcat[i] = tfr(v);
        return;
    }
    i -= N0;
    if (i < N1) { g_Wor[i]   = tfr(Wo[i]);   return; } i -= N1;
    if (i < N2) { g_Wff1r[i] = tfr(Wff1[i]); return; } i -= N2;
    if (i < N3) { g_Wff2r[i] = tfr(Wff2[i]); return; } i -= N3;
    if (i < N4) { g_Wfusr[i] = tfr(Wfus[i]); }
}

// ------------------------- one-time: emb of obs frames (per l,b) ------------------
__global__ void k_eobs(const float* __restrict__ obs, const float* __restrict__ Wemb,
                       const float* __restrict__ bemb)
{
    int r = blockIdx.x, t = threadIdx.x;   // r = l*NB + b, t < 32
    float o0 = obs[r * 2 + 0], o1 = obs[r * 2 + 1];
    g_eobs[r * 32 + t] = fmaxf(o0 * Wemb[t] + o1 * Wemb[32 + t] + bemb[t], 0.f);
}

// ----------------- one-time: init emb/last + prep for f = OBS ---------------------
__global__ void k_initprep(const float* __restrict__ obs, const float* __restrict__ Wemb,
                           const float* __restrict__ bemb,
                           const float* __restrict__ loc, const float* __restrict__ feat,
                           const float* __restrict__ Wfus)
{
    int bm = blockIdx.x, tid = threadIdx.x;
    int b = bm & 255, m = bm >> 8;
    float lx = obs[((OBS - 1) * NB + b) * 2 + 0];
    float ly = obs[((OBS - 1) * NB + b) * 2 + 1];
    __shared__ float se[32], ex[32];
    if (tid < 32) {
        float e = fmaxf(lx * Wemb[tid] + ly * Wemb[32 + tid] + bemb[tid], 0.f);
        se[tid] = e;
        g_emb[bm * 32 + tid] = e;
    }
    if (tid < 2) g_last[bm * 2 + tid] = obs[((OBS - 1) * NB + b) * 2 + tid];
    float gx = loc[(b * NM + m) * 2 + 0], gy = loc[(b * NM + m) * 2 + 1];
    float dx = gx - lx, dy = gy - ly;
    float t = (float)OBS;
    __syncthreads();
    if (tid < 32) {
        float v;
        if (tid < 8)       v = (tid & 1) ? gy : gx;
        else if (tid < 16) v = (tid & 1) ? ly : lx;
        else if (tid < 24) v = (tid & 1) ? dy : dx;
        else               v = t;
        ex[tid] = v;
        g_E[bm * 64 + tid] = tfr(v);
        g_E[bm * 64 + 32 + tid] = tfr(se[tid]);
    }
    __syncthreads();
    for (int c = tid; c < 512; c += 128) {
        float v;
        if (c < 32)      v = se[c];
        else if (c < 64) v = ex[c - 32];
        else             v = feat[b * INC + (c - 64)];
        g_xlast[bm * 512 + c] = v;
    }
    for (int c = tid; c < 448; c += 128) {
        float v = g_cffus[b * 448 + c];
        v += lx * Wfus[(512 + 0) * 448 + c];
        v += ly * Wfus[(512 + 1) * 448 + c];
        v += gx * Wfus[(512 + 2) * 448 + c];
        v += gy * Wfus[(512 + 3) * 448 + c];
        v += dx * Wfus[(512 + 4) * 448 + c];
        v += dy * Wfus[(512 + 5) * 448 + c];
        v += t  * Wfus[(512 + 6) * 448 + c];
        g_rowfus[bm * 448 + c] = v;
    }
}

// ------------------------- per-step attention -------------------------------------
__global__ void k_attn(int f)
{
    int bm = blockIdx.x;
    int tid = threadIdx.x, w = tid >> 5, lane = tid & 31;
    int b = bm & 255;
    const float* qp = g_QKVC + (size_t)bm * 1536 + w * 64;
    float q0 = qp[2 * lane], q1 = qp[2 * lane + 1];
    const float* ckp = qp + 512;
    float s = q0 * ckp[2 * lane] + q1 * ckp[2 * lane + 1];
#pragma unroll
    for (int o = 16; o; o >>= 1) s += __shfl_xor_sync(0xffffffffu, s, o);
    const float qdot = s;
    __shared__ float sp[8][56];
    const int off = w * 64 + 2 * lane;
    const __nv_bfloat16* ob = g_eKVo + (size_t)b * 1024 + off;
    const __nv_bfloat16* rb = g_eKV + (size_t)bm * 1024 + off;
    const int fr = f - OBS;
    for (int l = 0; l < OBS; l++) {
        float2 kf = __bfloat1622float2(*(const __nv_bfloat162*)(ob + (size_t)l * NB * 1024));
        float d = q0 * kf.x + q1 * kf.y;
#pragma unroll
        for (int o = 16; o; o >>= 1) d += __shfl_xor_sync(0xffffffffu, d, o);
        if (lane == 0) sp[w][l] = (d + qdot) * 0.125f;
    }
    for (int l = 0; l < fr; l++) {
        float2 kf = __bfloat1622float2(*(const __nv_bfloat162*)(rb + (size_t)l * BMT * 1024));
        float d = q0 * kf.x + q1 * kf.y;
#pragma unroll
        for (int o = 16; o; o >>= 1) d += __shfl_xor_sync(0xffffffffu, d, o);
        if (lane == 0) sp[w][OBS + l] = (d + qdot) * 0.125f;
    }
    __syncwarp();
    float mx = -1e30f;
    if (lane < f)      mx = sp[w][lane];
    if (lane + 32 < f) mx = fmaxf(mx, sp[w][lane + 32]);
#pragma unroll
    for (int o = 16; o; o >>= 1) mx = fmaxf(mx, __shfl_xor_sync(0xffffffffu, mx, o));
    float e0 = 0.f, e1 = 0.f;
    if (lane < f)      e0 = expf(sp[w][lane] - mx);
    if (lane + 32 < f) e1 = expf(sp[w][lane + 32] - mx);
    float sum = e0 + e1;
#pragma unroll
    for (int o = 16; o; o >>= 1) sum += __shfl_xor_sync(0xffffffffu, sum, o);
    if (lane < f)      sp[w][lane] = e0;
    if (lane + 32 < f) sp[w][lane + 32] = e1;
    __syncwarp();
    float inv = 1.f / sum;
    const float* cvp = qp + 1024;
    float a0 = 0.f, a1 = 0.f;
    for (int l = 0; l < OBS; l++) {
        float p = sp[w][l];
        float2 vf = __bfloat1622float2(*(const __nv_bfloat162*)(ob + 512 + (size_t)l * NB * 1024));
        a0 += p * vf.x;
        a1 += p * vf.y;
    }
    for (int l = 0; l < fr; l++) {
        float p = sp[w][OBS + l];
        float2 vf = __bfloat1622float2(*(const __nv_bfloat162*)(rb + 512 + (size_t)l * BMT * 1024));
        a0 += p * vf.x;
        a1 += p * vf.y;
    }
    float* op = g_ctx + (size_t)bm * 512 + off;
    *(float2*)op = make_float2(tfr(cvp[2 * lane] + a0 * inv),
                               tfr(cvp[2 * lane + 1] + a1 * inv));
}

// ------------------ layernorm over 512: out = tf32(LN(x1+x2+x3)*g+b) --------------
__global__ void k_ln(const float* __restrict__ x1, const float* __restrict__ x2,
                     const float* __restrict__ x3,
                     const float* __restrict__ g, const float* __restrict__ bb,
                     float* __restrict__ out)
{
    int row = blockIdx.x, tid = threadIdx.x;
    __shared__ float red[256];
    size_t base = (size_t)row * 512;
    float v0 = x1[base + tid]       + x2[base + tid]       + x3[base + tid];
    float v1 = x1[base + tid + 256] + x2[base + tid + 256] + x3[base + tid + 256];
    red[tid] = v0 + v1;
    __syncthreads();
    for (int s = 128; s; s >>= 1) { if (tid < s) red[tid] += red[tid + s]; __syncthreads(); }
    float mu = red[0] * (1.f / 512.f);
    __syncthreads();
    float d0 = v0 - mu, d1 = v1 - mu;
    red[tid] = d0 * d0 + d1 * d1;
    __syncthreads();
    for (int s = 128; s; s >>= 1) { if (tid < s) red[tid] += red[tid + s]; __syncthreads(); }
    float rs = rsqrtf(red[0] * (1.f / 512.f) + 1e-5f);
    out[base + tid]       = tfr(d0 * rs * g[tid] + bb[tid]);
    out[base + tid + 256] = tfr(d1 * rs * g[tid + 256] + bb[tid + 256]);
}

// ---- fused per-step epilogue: out + emb + prep for step f+1 ---------------------
__global__ void k_step(const float* __restrict__ Wout, const float* __restrict__ bout,
                       const float* __restrict__ Wemb, const float* __restrict__ bemb,
                       const float* __restrict__ loc, const float* __restrict__ feat,
                       const float* __restrict__ Wfus,
                       float* __restrict__ dout, int f)
{
    int bm = blockIdx.x, tid = threadIdx.x;
    int b = bm & 255, m = bm >> 8;
    __shared__ float r0[128], r1[128];
    __shared__ float se[32], ex[32];

    float s0 = 0.f, s1 = 0.f;
    const float* fp  = g_fus  + (size_t)bm * 448;
    const float* fpb = g_fusb + (size_t)bm * 448;
    for (int c = tid; c < 448; c += 128) {
        float v = fp[c] + fpb[c];
        s0 += v * Wout[c * 2 + 0];
        s1 += v * Wout[c * 2 + 1];
    }
    r0[tid] = s0; r1[tid] = s1;
    __syncthreads();
    for (int s = 64; s; s >>= 1) {
        if (tid < s) { r0[tid] += r0[tid + s]; r1[tid] += r1[tid + s]; }
        __syncthreads();
    }
    float o0 = r0[0] + bout[0];
    float o1 = r1[0] + bout[1];

    if (tid < 32) {
        float e = fmaxf(o0 * Wemb[tid] + o1 * Wemb[32 + tid] + bemb[tid], 0.f);
        se[tid] = e;
        g_emb[bm * 32 + tid] = e;
    }
    if (tid == 0) {
        g_last[bm * 2 + 0] = o0;
        g_last[bm * 2 + 1] = o1;
        int t = f - OBS;
        dout[b * (NM * HOR * 2) + m * (HOR * 2) + t * 2 + 0] = o0;
        dout[b * (NM * HOR * 2) + m * (HOR * 2) + t * 2 + 1] = o1;
    }
    __syncthreads();

    int fn = f + 1;
    if (fn < OBS + HOR) {
        float gx = loc[(b * NM + m) * 2 + 0], gy = loc[(b * NM + m) * 2 + 1];
        float dx = gx - o0, dy = gy - o1;
        float t = (float)fn;
        if (tid < 32) {
            float v;
            if (tid < 8)       v = (tid & 1) ? gy : gx;
            else if (tid < 16) v = (tid & 1) ? o1 : o0;
            else if (tid < 24) v = (tid & 1) ? dy : dx;
            else               v = t;
            ex[tid] = v;
            g_E[bm * 64 + tid] = tfr(v);
            g_E[bm * 64 + 32 + tid] = tfr(se[tid]);
        }
        __syncthreads();
        for (int c = tid; c < 512; c += 128) {
            float v;
            if (c < 32)      v = se[c];
            else if (c < 64) v = ex[c - 32];
            else             v = feat[b * INC + (c - 64)];
            g_xlast[bm * 512 + c] = v;
        }
        for (int c = tid; c < 448; c += 128) {
            float v = g_cffus[b * 448 + c];
            v += o0 * Wfus[(512 + 0) * 448 + c];
            v += o1 * Wfus[(512 + 1) * 448 + c];
            v += gx * Wfus[(512 + 2) * 448 + c];
            v += gy * Wfus[(512 + 3) * 448 + c];
            v += dx * Wfus[(512 + 4) * 448 + c];
            v += dy * Wfus[(512 + 5) * 448 + c];
            v += t  * Wfus[(512 + 6) * 448 + c];
            g_rowfus[bm * 448 + c] = v;
        }
    }
}

// ----------------------------------- launch ---------------------------------------
extern "C" void kernel_launch(void* const* d_in, const int* in_sizes, int n_in,
                              void* d_out, int out_size)
{
    const float* feat = (const float*)d_in[0];
    const float* loc  = (const float*)d_in[1];
    const float* obs  = (const float*)d_in[2];
    const float* Wemb = (const float*)d_in[3];
    const float* bemb = (const float*)d_in[4];
    const float* Wqkv = (const float*)d_in[5];
    const float* bqkv = (const float*)d_in[6];
    const float* Wo   = (const float*)d_in[7];
    const float* bo   = (const float*)d_in[8];
    const float* Wff1 = (const float*)d_in[9];
    const float* bff1 = (const float*)d_in[10];
    const float* Wff2 = (const float*)d_in[11];
    const float* bff2 = (const float*)d_in[12];
    const float* ln1g = (const float*)d_in[13];
    const float* ln1b = (const float*)d_in[14];
    const float* ln2g = (const float*)d_in[15];
    const float* ln2b = (const float*)d_in[16];
    const float* Wfus = (const float*)d_in[17];
    const float* bfus = (const float*)d_in[18];
    const float* Wout = (const float*)d_in[19];
    const float* bout = (const float*)d_in[20];
    float* outp = (float*)d_out;

    float *cfeat, *cffus, *Wcat, *Wor, *Wff1r, *Wff2r, *Wfusr, *eobs, *E, *xlast,
          *rowfus, *QKVC, *ctx, *wo, *wob, *h1, *ff1, *ff2, *ff2b, *h2, *fus, *fusb;
    __nv_bfloat16 *eKV, *eKVo;
    cudaGetSymbolAddress((void**)&cfeat,  g_cfeat);
    cudaGetSymbolAddress((void**)&cffus,  g_cffus);
    cudaGetSymbolAddress((void**)&Wcat,   g_Wcat);
    cudaGetSymbolAddress((void**)&Wor,    g_Wor);
    cudaGetSymbolAddress((void**)&Wff1r,  g_Wff1r);
    cudaGetSymbolAddress((void**)&Wff2r,  g_Wff2r);
    cudaGetSymbolAddress((void**)&Wfusr,  g_Wfusr);
    cudaGetSymbolAddress((void**)&eobs,   g_eobs);
    cudaGetSymbolAddress((void**)&eKV,    g_eKV);
    cudaGetSymbolAddress((void**)&eKVo,   g_eKVo);
    cudaGetSymbolAddress((void**)&E,      g_E);
    cudaGetSymbolAddress((void**)&xlast,  g_xlast);
    cudaGetSymbolAddress((void**)&rowfus, g_rowfus);
    cudaGetSymbolAddress((void**)&QKVC,   g_QKVC);
    cudaGetSymbolAddress((void**)&ctx,    g_ctx);
    cudaGetSymbolAddress((void**)&wo,     g_wo);
    cudaGetSymbolAddress((void**)&wob,    g_wob);
    cudaGetSymbolAddress((void**)&h1,     g_h1);
    cudaGetSymbolAddress((void**)&ff1,    g_ff1);
    cudaGetSymbolAddress((void**)&ff2,    g_ff2);
    cudaGetSymbolAddress((void**)&ff2b,   g_ff2b);
    cudaGetSymbolAddress((void**)&h2,     g_h2);
    cudaGetSymbolAddress((void**)&fus,    g_fus);
    cudaGetSymbolAddress((void**)&fusb,   g_fusb);

    const float* NUL = (const float*)0;
    float* FNUL = (float*)0;
    __nv_bfloat16* BNUL = (__nv_bfloat16*)0;

    const int SMEM128 = 3 * (128 * 36 + 32 * 132) * 4;  // 105984
    const int SMEM64  = 3 * (128 * 36 + 32 * 68) * 4;   // 81408
    cudaFuncSetAttribute(k_gemmp<128>, cudaFuncAttributeMaxDynamicSharedMemorySize, SMEM128);
    cudaFuncSetAttribute(k_gemmp<64>,  cudaFuncAttributeMaxDynamicSharedMemorySize, SMEM64);

    // ---- setup: exactly 5 launches so ncu (-s 5 -c 1) profiles the QKVC GEMM ----
    const int NSET = 64 * 2560 + 512 * 512 + 512 * 2048 + 2048 * 512 + 512 * 448;
    k_setup<<<(NSET + 255) / 256, 256>>>(Wqkv, Wo, Wff1, Wff2, Wfus);           // 1
    k_eobs<<<OBS * NB, 32>>>(obs, Wemb, bemb);                                  // 2
    // cfeat (z=0) + cffus (z=1), both 256 rows, K=448
    k_gemm0d<<<dim3(24, 2, 2), 256>>>(feat, 448, 448,                           // 3
                                      Wqkv + 64 * 1536, 1536, cfeat, 1536, bqkv, 24,
                                      Wfus + 519 * 448, 448, cffus, 448, bfus, 7);
    // eKVo = eobs @ W_qkv[0:32, 512:1536]  (5120 x 1024, K=32, bf16 out)
    k_gemm0<<<dim3(16, 40), 256>>>(eobs, 32, Wqkv + 512, 1536,                  // 4
                                   eKVo, 1024, 32, NUL, 1);
    k_initprep<<<BMT, 128>>>(obs, Wemb, bemb, loc, feat, Wfus);                 // 5

    for (int f = OBS; f < OBS + HOR; f++) {
        // fused: QKVC = E @ Wcat[:, :1536] + cfeat;  eKV[f-1] = E @ Wcat[:, 1536:]
        __nv_bfloat16* ekdst = (f == OBS) ? (__nv_bfloat16*)wob
                                          : eKV + (size_t)(f - 1 - OBS) * BMT * 1024;
        k_gemmp<128><<<dim3(20, 12), 256, SMEM128>>>(E, 64, Wcat, 2560, QKVC, 1536, 64,
                                                     NUL, cfeat, 256, 1536, 0, 0, FNUL,
                                                     ekdst, 1536);
        k_attn<<<BMT, 256>>>(f);
        // wo(+wob) = ctx @ W_o + b_o           (1536 x 512, K=512, split-K)
        k_gemmp<64><<<dim3(8, 12, 2), 256, SMEM64>>>(ctx, 512, Wor, 512, wo, 512, 256,
                                                     bo, NUL, 1, 0, 0, 0, wob, BNUL, 1 << 30);
        k_ln<<<BMT, 256>>>(xlast, wo, wob, ln1g, ln1b, h1);
        // ff1 = tf32(relu(h1 @ W_ff1 + b_ff1)) (1536 x 2048, K=512)
        k_gemmp<128><<<dim3(16, 12), 256, SMEM128>>>(h1, 512, Wff1r, 2048, ff1, 2048, 512,
                                                     bff1, NUL, 1, 0, 1, 1, FNUL, BNUL, 1 << 30);
        // ff2(+ff2b) = ff1 @ W_ff2 + b_ff2     (1536 x 512, K=2048, split-K)
        k_gemmp<64><<<dim3(8, 12, 2), 256, SMEM64>>>(ff1, 2048, Wff2r, 512, ff2, 512, 1024,
                                                     bff2, NUL, 1, 0, 0, 0, ff2b, BNUL, 1 << 30);
        k_ln<<<BMT, 256>>>(h1, ff2, ff2b, ln2g, ln2b, h2);
        // fus(+fusb) = h2 @ W_fus[0:512,:] + rowfus  (1536 x 448, K=512, split-K)
        k_gemmp<64><<<dim3(7, 12, 2), 256, SMEM64>>>(h2, 512, Wfusr, 448, fus, 448, 256,
                                                     NUL, rowfus, BMT, 448, 0, 0, fusb,
                                                     BNUL, 1 << 30);
        // fused: out + emb + prep(f+1)
        k_step<<<BMT, 128>>>(Wout, bout, Wemb, bemb, loc, feat, Wfus, outp, f);
    }
    (void)in_sizes; (void)n_in; (void)out_size;
}